// round 15
// baseline (speedup 1.0000x reference)
#include <cuda_runtime.h>
#include <cuda_fp16.h>

typedef unsigned int uint32;

#define BN 8192
#define TN 2048
#define MPC 16   // muscles per CTA — all 16 rows of the MMA tile

// Transposed excitation scratch: [T][B] layout for coalesced per-step loads.
__device__ float g_excT[(size_t)TN * BN];

__device__ __forceinline__ float tanha(float x) {
    float y; asm("tanh.approx.f32 %0, %1;" : "=f"(y) : "f"(x)); return y;
}
__device__ __forceinline__ uint32 packh2(float lo, float hi) {
    __half2 h = __floats2half2_rn(lo, hi);
    return *(uint32*)&h;
}

// exc[B][T] -> g_excT[T][B]
__global__ void transpose_exc(const float* __restrict__ exc) {
    __shared__ float tile[32][33];
    int t0 = blockIdx.x * 32, b0 = blockIdx.y * 32;
    int tx = threadIdx.x, ty = threadIdx.y;
#pragma unroll
    for (int i = 0; i < 32; i += 8)
        tile[ty + i][tx] = exc[(size_t)(b0 + ty + i) * TN + t0 + tx];
    __syncthreads();
#pragma unroll
    for (int i = 0; i < 32; i += 8)
        g_excT[(size_t)(t0 + ty + i) * BN + b0 + tx] = tile[tx][ty + i];
}

// Full-tile tensor-core formulation with replicated (non-divergent)
// physics. CTA = 128 threads (4 warps), 16 muscles = the full 16-row
// A tile. Each warp owns a 16-wide N-slice of the [16x64]x[64x64] fp16
// MMA (2 n-tiles x 4 ck = 8 HMMA), W2 fragments resident in registers.
// Physics/RK4 state is replicated: warp w handles muscles
// (w&1)*8 + (lane&7); 8 replicas per muscle; stores predicated on the
// warp<2, lane<8 replica. Physics overlaps the HMMA dependency chain.
// The epilogue consumes all 4 C-regs (two muscle rows, same columns ->
// same W3/b2 registers). No launch_bounds reg cap.
__global__ __launch_bounds__(128) void ode_kernel(
    const float* __restrict__ init, const float* __restrict__ tspan,
    const float* __restrict__ W1, const float* __restrict__ b1,
    const float* __restrict__ W2, const float* __restrict__ b2,
    const float* __restrict__ W3, const float* __restrict__ b3,
    float* __restrict__ out)
{
    __shared__ __align__(128) __half h_s[16 * 64];  // A tile, 128B row stride
    __shared__ __align__(16) float pp[4 * 16 * 4];  // partials [warp][m][4]
    __shared__ __align__(16) float x_s[MPC * 4];
    __shared__ __align__(16) float sb3[4];

    const int tid  = threadIdx.x;
    const int lane = tid & 31;
    const int warp = tid >> 5;
    const int jg   = tid & 63;            // layer-1 output-neuron index
    const int mgrp = tid >> 6;            // layer-1 muscle group (0 / 1)

    if (tid < 3) sb3[tid] = b3[tid];
    if (tid == 3) sb3[3] = 0.0f;

    // layer-1 column for this thread's neuron
    const float w10 = W1[jg], w11 = W1[64 + jg],
                w12 = W1[128 + jg], w13 = W1[192 + jg];
    const float b1j = b1[jg];

    // W2 B-fragments (m16n8k16 col layout): n = warp*16 + nt*8 + lane/4,
    // k = ck*16 + (lane%4)*2 (+1, +8, +9). 8 fragments x 2 regs.
    uint32 bfrag[2][4][2];
#pragma unroll
    for (int nt = 0; nt < 2; nt++) {
#pragma unroll
        for (int ck = 0; ck < 4; ck++) {
            int n  = warp * 16 + nt * 8 + (lane >> 2);
            int k0 = ck * 16 + (lane & 3) * 2;
            bfrag[nt][ck][0] = packh2(W2[k0 * 64 + n], W2[(k0 + 1) * 64 + n]);
            bfrag[nt][ck][1] = packh2(W2[(k0 + 8) * 64 + n], W2[(k0 + 9) * 64 + n]);
        }
    }
    // layer-3 weights + b2 for this lane's output columns:
    // j0 = warp*16 + nt*8 + (lane%4)*2, j1 = j0+1 (same for both C rows)
    float w3a[2][3], w3b[2][3];
    float2 b2v[2];
#pragma unroll
    for (int nt = 0; nt < 2; nt++) {
        int j0 = warp * 16 + nt * 8 + (lane & 3) * 2;
#pragma unroll
        for (int c = 0; c < 3; c++) {
            w3a[nt][c] = W3[j0 * 3 + c];
            w3b[nt][c] = W3[(j0 + 1) * 3 + c];
        }
        b2v[nt] = make_float2(b2[j0], b2[j0 + 1]);
    }

    const uint32 hbase = (uint32)__cvta_generic_to_shared(h_s);
    const uint32 a_addr = hbase + (lane & 15) * 128 + (lane >> 4) * 16;

    // replicated muscle assignment: 8 replicas per muscle
    const int  mo = (warp & 1) * 8 + (lane & 7);   // muscle of this replica
    const bool rep0 = (warp < 2) && (lane < 8);    // the storing replica
    const int  bo = blockIdx.x * MPC + mo;

    float y0 = init[bo * 3 + 0];
    float y1 = init[bo * 3 + 1];
    float y2 = init[bo * 3 + 2];
    float ep = g_excT[bo];               // k1 at step 0 uses exc[:, 0]
    float tprev = tspan[0];
    if (rep0) {
        out[bo * 3 + 0] = y0; out[bo * 3 + 1] = y1; out[bo * 3 + 2] = y2;
        *(float4*)(x_s + mo * 4) = make_float4(y0, y1, y2, ep);
    }
    __syncthreads();

#pragma unroll 1
    for (int it = 0; it < TN - 1; it++) {
        float ec    = g_excT[(size_t)it * BN + bo];  // exc[:, it] for k2/k3/k4
        float tnext = tspan[it + 1];
        float dt    = tnext - tprev;
        tprev = tnext;
        float hd  = 0.5f * dt;
        float a0s = y0, a1s = y1, a2s = y2;
        float s0 = 0.f, s1 = 0.f, s2 = 0.f;

#pragma unroll 1
        for (int sg = 0; sg < 4; sg++) {
            // ---- slot 1: layer-1, muscle-group split across thread halves ----
#pragma unroll
            for (int mm = 0; mm < 8; mm++) {
                int m = mgrp * 8 + mm;
                float4 x = *(const float4*)(x_s + m * 4);   // broadcast
                float t = fmaf(x.x, w10,
                          fmaf(x.y, w11,
                          fmaf(x.z, w12,
                          fmaf(x.w, w13, b1j))));
                h_s[m * 64 + jg] = __float2half(tanha(t));
            }
            __syncthreads();

            // ---- slot 2: HMMA issue, physics overlapped, fused epilogue ----
            float c[2][4];
#pragma unroll
            for (int nt = 0; nt < 2; nt++)
                c[nt][0] = c[nt][1] = c[nt][2] = c[nt][3] = 0.0f;
#pragma unroll
            for (int ck = 0; ck < 4; ck++) {
                uint32 af0, af1, af2, af3;
                asm volatile(
                    "ldmatrix.sync.aligned.m8n8.x4.shared.b16 {%0,%1,%2,%3}, [%4];"
                    : "=r"(af0), "=r"(af1), "=r"(af2), "=r"(af3)
                    : "r"(a_addr + ck * 32));
#pragma unroll
                for (int nt = 0; nt < 2; nt++) {
                    asm volatile(
                        "mma.sync.aligned.m16n8k16.row.col.f32.f16.f16.f32 "
                        "{%0,%1,%2,%3}, {%4,%5,%6,%7}, {%8,%9}, {%0,%1,%2,%3};"
                        : "+f"(c[nt][0]), "+f"(c[nt][1]),
                          "+f"(c[nt][2]), "+f"(c[nt][3])
                        : "r"(af0), "r"(af1), "r"(af2), "r"(af3),
                          "r"(bfrag[nt][ck][0]), "r"(bfrag[nt][ck][1]));
                }
            }

            // physics (ALL lanes, straight-line; overlaps HMMA latency)
            float k0, k1d, k2d;
            {
                float e = (sg == 0) ? ep : ec;
                float lM   = fminf(fmaxf(a0s, 0.0445f), 0.1424f);
                float act  = fminf(fmaxf(a1s, 0.01f), 1.0f);
                float fat  = fminf(fmaxf(a2s, 0.0f), 1.0f);
                float aeff = act * (1.0f - fat);
                // L0*sin(PENN0) = 0.089*sin(0.0873)
                float sinp = fminf(__fdividef(0.00775983457f, lM), 0.99f);
                float cosp = sqrtf(1.0f - sinp * sinp);
                // LMT_DEFAULT = 0.126 + 0.089*cos(0.0873)
                float lT   = 0.214661068f - lM * cosp;
                float epsT = (lT - 0.126f) * (1.0f / 0.126f);
                float fT   = (epsT > 0.0f) ? 0.2f * (__expf(35.0f * epsT) - 1.0f) : 0.0f;
                float lN   = lM * (1.0f / 0.089f);
                float ddv  = lN - 1.0f;
                float fL   = __expf(-ddv * ddv * (1.0f / 0.45f));
                float fPE  = (lN > 1.0f)
                           ? (__expf(ddv * (5.0f / 0.6f)) - 1.0f) * (1.0f / 147.4131591f)
                           : 0.0f;
                float fV   = __fdividef(__fdividef(fT, cosp) - fPE, aeff * fL + 0.001f);
                float vN   = fminf(fmaxf(__fdividef(fV - 1.0f, 1.0f + fabsf(fV) * 4.0f),
                                         -1.0f), 1.5f);
                k0   = 0.89f * vN;                        // VMAX*L0*vN
                float tau = (e > act) ? 0.01f * (0.5f + 1.5f * act)
                                      : __fdividef(0.04f, 0.5f + 1.5f * act);
                k1d  = __fdividef(e - act, tau);
                k2d  = 0.01f * aeff * (1.0f - fat) - 0.002f * (1.0f - aeff) * fat;
            }

            // epilogue: muscle A = lane>>2 (c0,c1), muscle B = 8+(lane>>2)
            // (c2,c3); both rows share the same columns / W3 / b2.
            float pA0 = 0.f, pA1 = 0.f, pA2 = 0.f;
            float pB0 = 0.f, pB1 = 0.f, pB2 = 0.f;
#pragma unroll
            for (int nt = 0; nt < 2; nt++) {
                float oA0 = tanha(c[nt][0] + b2v[nt].x);
                float oA1 = tanha(c[nt][1] + b2v[nt].y);
                float oB0 = tanha(c[nt][2] + b2v[nt].x);
                float oB1 = tanha(c[nt][3] + b2v[nt].y);
                pA0 = fmaf(oA0, w3a[nt][0], fmaf(oA1, w3b[nt][0], pA0));
                pA1 = fmaf(oA0, w3a[nt][1], fmaf(oA1, w3b[nt][1], pA1));
                pA2 = fmaf(oA0, w3a[nt][2], fmaf(oA1, w3b[nt][2], pA2));
                pB0 = fmaf(oB0, w3a[nt][0], fmaf(oB1, w3b[nt][0], pB0));
                pB1 = fmaf(oB0, w3a[nt][1], fmaf(oB1, w3b[nt][1], pB1));
                pB2 = fmaf(oB0, w3a[nt][2], fmaf(oB1, w3b[nt][2], pB2));
            }
            // interleaved quad reductions (6 independent chains)
            pA0 += __shfl_xor_sync(0xffffffffu, pA0, 1);
            pA1 += __shfl_xor_sync(0xffffffffu, pA1, 1);
            pA2 += __shfl_xor_sync(0xffffffffu, pA2, 1);
            pB0 += __shfl_xor_sync(0xffffffffu, pB0, 1);
            pB1 += __shfl_xor_sync(0xffffffffu, pB1, 1);
            pB2 += __shfl_xor_sync(0xffffffffu, pB2, 1);
            pA0 += __shfl_xor_sync(0xffffffffu, pA0, 2);
            pA1 += __shfl_xor_sync(0xffffffffu, pA1, 2);
            pA2 += __shfl_xor_sync(0xffffffffu, pA2, 2);
            pB0 += __shfl_xor_sync(0xffffffffu, pB0, 2);
            pB1 += __shfl_xor_sync(0xffffffffu, pB1, 2);
            pB2 += __shfl_xor_sync(0xffffffffu, pB2, 2);
            if ((lane & 3) == 0) {
                int mA = lane >> 2;
                *(float4*)(pp + (warp * 16 + mA) * 4) =
                    make_float4(pA0, pA1, pA2, 0.0f);
                *(float4*)(pp + (warp * 16 + 8 + mA) * 4) =
                    make_float4(pB0, pB1, pB2, 0.0f);
            }
            __syncthreads();

            // ---- slot 3: combine 4 warp-partials + RK4 (ALL lanes) ----
            {
                float4 q0 = *(const float4*)(pp + mo * 4);
                float4 q1 = *(const float4*)(pp + (16 + mo) * 4);
                float4 q2 = *(const float4*)(pp + (32 + mo) * 4);
                float4 q3 = *(const float4*)(pp + (48 + mo) * 4);
                float pa = (q0.x + q1.x) + (q2.x + q3.x);
                float pb = (q0.y + q1.y) + (q2.y + q3.y);
                float pc = (q0.z + q1.z) + (q2.z + q3.z);

                k0  += 0.2f * (0.1f * tanha(pa + sb3[0]));
                k1d += 0.2f * (0.1f * tanha(pb + sb3[1]));
                k2d += 0.2f * (0.1f * tanha(pc + sb3[2]));

                float wgt = (sg == 1 || sg == 2) ? 2.0f : 1.0f;
                s0 = fmaf(wgt, k0,  s0);
                s1 = fmaf(wgt, k1d, s1);
                s2 = fmaf(wgt, k2d, s2);

                if (sg < 3) {
                    float st = (sg < 2) ? hd : dt;
                    a0s = y0 + st * k0;
                    a1s = y1 + st * k1d;
                    a2s = y2 + st * k2d;
                    if (rep0)
                        *(float4*)(x_s + mo * 4) = make_float4(a0s, a1s, a2s, ec);
                } else {
                    float w6 = dt * (1.0f / 6.0f);
                    y0 += w6 * s0; y1 += w6 * s1; y2 += w6 * s2;
                    if (rep0) {
                        size_t o = (size_t)(it + 1) * (BN * 3) + (size_t)bo * 3;
                        out[o] = y0; out[o + 1] = y1; out[o + 2] = y2;
                        // next step's k1 excitation = this step's ec
                        *(float4*)(x_s + mo * 4) = make_float4(y0, y1, y2, ec);
                    }
                }
            }
            __syncthreads();
        }
        ep = ec;
    }
}

extern "C" void kernel_launch(void* const* d_in, const int* in_sizes, int n_in,
                              void* d_out, int out_size) {
    const float* init = (const float*)d_in[0];
    const float* exc  = (const float*)d_in[1];
    const float* ts   = (const float*)d_in[2];
    const float* W1   = (const float*)d_in[3];
    const float* b1   = (const float*)d_in[4];
    const float* W2   = (const float*)d_in[5];
    const float* b2   = (const float*)d_in[6];
    const float* W3   = (const float*)d_in[7];
    const float* b3   = (const float*)d_in[8];
    float* out = (float*)d_out;

    dim3 tb(32, 8);
    dim3 tg(TN / 32, BN / 32);
    transpose_exc<<<tg, tb>>>(exc);
    ode_kernel<<<BN / MPC, 128>>>(init, ts, W1, b1, W2, b2, W3, b3, out);
}

// round 16
// speedup vs baseline: 1.3010x; 1.3010x over previous
#include <cuda_runtime.h>
#include <cuda_fp16.h>

typedef unsigned int uint32;

#define BN 8192
#define TN 2048
#define MPC 8    // muscles per CTA (rows 0..7 of the 16-row MMA tile)

// Transposed excitation scratch: [T][B] layout for coalesced per-step loads.
__device__ float g_excT[(size_t)TN * BN];

__device__ __forceinline__ float tanha(float x) {
    float y; asm("tanh.approx.f32 %0, %1;" : "=f"(y) : "f"(x)); return y;
}
__device__ __forceinline__ uint32 packh2(float lo, float hi) {
    __half2 h = __floats2half2_rn(lo, hi);
    return *(uint32*)&h;
}

// exc[B][T] -> g_excT[T][B]
__global__ void transpose_exc(const float* __restrict__ exc) {
    __shared__ float tile[32][33];
    int t0 = blockIdx.x * 32, b0 = blockIdx.y * 32;
    int tx = threadIdx.x, ty = threadIdx.y;
#pragma unroll
    for (int i = 0; i < 32; i += 8)
        tile[ty + i][tx] = exc[(size_t)(b0 + ty + i) * TN + t0 + tx];
    __syncthreads();
#pragma unroll
    for (int i = 0; i < 32; i += 8)
        g_excT[(size_t)(t0 + ty + i) * BN + b0 + tx] = tile[tx][ty + i];
}

// Tensor-core formulation, 2 barriers per stage. CTA = 64 threads
// (2 warps), 8 muscles. Layer-2 = [16x64]x[64x64] fp16 MMA (rows 8-15
// zero), W2 fragments resident in registers (each warp owns a 32-wide
// N-half). Physics/RK4 state is replicated with mo = lane&7: EACH warp
// redundantly integrates ALL 8 muscles (4 replicas per muscle per warp,
// same per-warp instruction count as before). This makes the muscle
// state exchange warp-private (x_sw[warp], written by lanes 0-7, read
// by the same warp) so the slot3->slot1 __syncthreads becomes a
// __syncwarp. Remaining CTA barriers: after h_s store (pre-ldmatrix)
// and after pp store (pre-combine). Physics overlaps the HMMA chain.
__global__ __launch_bounds__(64, 7) void ode_kernel(
    const float* __restrict__ init, const float* __restrict__ tspan,
    const float* __restrict__ W1, const float* __restrict__ b1,
    const float* __restrict__ W2, const float* __restrict__ b2,
    const float* __restrict__ W3, const float* __restrict__ b3,
    float* __restrict__ out)
{
    __shared__ __align__(128) __half h_s[16 * 64];  // A tile, 128B row stride
    __shared__ __align__(16) float pp[16 * 4];      // partials [warp*8+m]
    __shared__ __align__(16) float x_sw[2][32];     // per-warp state buffers
    __shared__ __align__(16) float sb3[4];

    const int tid  = threadIdx.x;
    const int lane = tid & 31;
    const int warp = tid >> 5;
    const int jg   = tid;                 // layer-1 output-neuron index

    // zero the A tile once (rows 8-15 stay zero forever)
    for (int i = tid; i < 16 * 64; i += 64) h_s[i] = __float2half(0.0f);
    if (tid < 3) sb3[tid] = b3[tid];
    if (tid == 3) sb3[3] = 0.0f;

    // layer-1 column for this thread
    const float w10 = W1[jg], w11 = W1[64 + jg],
                w12 = W1[128 + jg], w13 = W1[192 + jg];
    const float b1j = b1[jg];

    // W2 B-fragments (m16n8k16, col layout): n = warp*32 + nt*8 + lane/4,
    // k = ck*16 + (lane%4)*2 (+1, +8, +9). 16 fragments x 2 regs.
    uint32 bfrag[4][4][2];
#pragma unroll
    for (int nt = 0; nt < 4; nt++) {
#pragma unroll
        for (int ck = 0; ck < 4; ck++) {
            int n  = warp * 32 + nt * 8 + (lane >> 2);
            int k0 = ck * 16 + (lane & 3) * 2;
            bfrag[nt][ck][0] = packh2(W2[k0 * 64 + n], W2[(k0 + 1) * 64 + n]);
            bfrag[nt][ck][1] = packh2(W2[(k0 + 8) * 64 + n], W2[(k0 + 9) * 64 + n]);
        }
    }
    // layer-3 weights + b2 for this lane's 8 output columns:
    // j0 = warp*32 + nt*8 + (lane%4)*2, j1 = j0+1  (C-fragment cols)
    float w3a[4][3], w3b[4][3];
    float2 b2v[4];
#pragma unroll
    for (int nt = 0; nt < 4; nt++) {
        int j0 = warp * 32 + nt * 8 + (lane & 3) * 2;
#pragma unroll
        for (int c = 0; c < 3; c++) {
            w3a[nt][c] = W3[j0 * 3 + c];
            w3b[nt][c] = W3[(j0 + 1) * 3 + c];
        }
        b2v[nt] = make_float2(b2[j0], b2[j0 + 1]);
    }

    const uint32 hbase = (uint32)__cvta_generic_to_shared(h_s);
    const uint32 a_addr = hbase + (lane & 15) * 128 + (lane >> 4) * 16;

    // replicated muscle assignment: each warp integrates all 8 muscles,
    // 4 replicas per muscle per warp
    const int  mo   = lane & 7;                    // muscle of this replica
    const bool repw = (lane < 8);                  // per-warp storing replica
    const bool rep0 = (warp == 0) && repw;         // global storing replica
    const int  bo = blockIdx.x * MPC + mo;

    float y0 = init[bo * 3 + 0];
    float y1 = init[bo * 3 + 1];
    float y2 = init[bo * 3 + 2];
    float ep = g_excT[bo];               // k1 at step 0 uses exc[:, 0]
    float tprev = tspan[0];
    if (repw)
        *(float4*)(&x_sw[warp][mo * 4]) = make_float4(y0, y1, y2, ep);
    if (rep0) {
        out[bo * 3 + 0] = y0; out[bo * 3 + 1] = y1; out[bo * 3 + 2] = y2;
    }
    __syncthreads();

#pragma unroll 1
    for (int it = 0; it < TN - 1; it++) {
        float ec    = g_excT[(size_t)it * BN + bo];  // exc[:, it] for k2/k3/k4
        float tnext = tspan[it + 1];
        float dt    = tnext - tprev;
        tprev = tnext;
        float hd  = 0.5f * dt;
        float a0s = y0, a1s = y1, a2s = y2;
        float s0 = 0.f, s1 = 0.f, s2 = 0.f;

#pragma unroll 1
        for (int sg = 0; sg < 4; sg++) {
            // ---- slot 1: layer-1 (all threads, warp-private x buffer) ----
            const float* xw = x_sw[warp];
#pragma unroll
            for (int m = 0; m < MPC; m++) {
                float4 x = *(const float4*)(xw + m * 4);    // broadcast
                float t = fmaf(x.x, w10,
                          fmaf(x.y, w11,
                          fmaf(x.z, w12,
                          fmaf(x.w, w13, b1j))));
                h_s[m * 64 + jg] = __float2half(tanha(t));
            }
            __syncthreads();                       // h visible to both warps

            // ---- slot 2: HMMA issue, physics overlapped, fused epilogue ----
            float c[4][4];
#pragma unroll
            for (int nt = 0; nt < 4; nt++)
                c[nt][0] = c[nt][1] = c[nt][2] = c[nt][3] = 0.0f;
#pragma unroll
            for (int ck = 0; ck < 4; ck++) {
                uint32 af0, af1, af2, af3;
                asm volatile(
                    "ldmatrix.sync.aligned.m8n8.x4.shared.b16 {%0,%1,%2,%3}, [%4];"
                    : "=r"(af0), "=r"(af1), "=r"(af2), "=r"(af3)
                    : "r"(a_addr + ck * 32));
#pragma unroll
                for (int nt = 0; nt < 4; nt++) {
                    asm volatile(
                        "mma.sync.aligned.m16n8k16.row.col.f32.f16.f16.f32 "
                        "{%0,%1,%2,%3}, {%4,%5,%6,%7}, {%8,%9}, {%0,%1,%2,%3};"
                        : "+f"(c[nt][0]), "+f"(c[nt][1]),
                          "+f"(c[nt][2]), "+f"(c[nt][3])
                        : "r"(af0), "r"(af1), "r"(af2), "r"(af3),
                          "r"(bfrag[nt][ck][0]), "r"(bfrag[nt][ck][1]));
                }
            }

            // physics (ALL lanes, straight-line; overlaps HMMA latency)
            float k0, k1d, k2d;
            {
                float e = (sg == 0) ? ep : ec;
                float lM   = fminf(fmaxf(a0s, 0.0445f), 0.1424f);
                float act  = fminf(fmaxf(a1s, 0.01f), 1.0f);
                float fat  = fminf(fmaxf(a2s, 0.0f), 1.0f);
                float aeff = act * (1.0f - fat);
                // L0*sin(PENN0) = 0.089*sin(0.0873)
                float sinp = fminf(__fdividef(0.00775983457f, lM), 0.99f);
                float cosp = sqrtf(1.0f - sinp * sinp);
                // LMT_DEFAULT = 0.126 + 0.089*cos(0.0873)
                float lT   = 0.214661068f - lM * cosp;
                float epsT = (lT - 0.126f) * (1.0f / 0.126f);
                float fT   = (epsT > 0.0f) ? 0.2f * (__expf(35.0f * epsT) - 1.0f) : 0.0f;
                float lN   = lM * (1.0f / 0.089f);
                float ddv  = lN - 1.0f;
                float fL   = __expf(-ddv * ddv * (1.0f / 0.45f));
                float fPE  = (lN > 1.0f)
                           ? (__expf(ddv * (5.0f / 0.6f)) - 1.0f) * (1.0f / 147.4131591f)
                           : 0.0f;
                float fV   = __fdividef(__fdividef(fT, cosp) - fPE, aeff * fL + 0.001f);
                float vN   = fminf(fmaxf(__fdividef(fV - 1.0f, 1.0f + fabsf(fV) * 4.0f),
                                         -1.0f), 1.5f);
                k0   = 0.89f * vN;                        // VMAX*L0*vN
                float tau = (e > act) ? 0.01f * (0.5f + 1.5f * act)
                                      : __fdividef(0.04f, 0.5f + 1.5f * act);
                k1d  = __fdividef(e - act, tau);
                k2d  = 0.01f * aeff * (1.0f - fat) - 0.002f * (1.0f - aeff) * fat;
            }

            // epilogue: this lane holds o-pre of muscle (lane>>2) at 8 cols
            float p0 = 0.f, p1 = 0.f, p2 = 0.f;
#pragma unroll
            for (int nt = 0; nt < 4; nt++) {
                float o0 = tanha(c[nt][0] + b2v[nt].x);
                float o1 = tanha(c[nt][1] + b2v[nt].y);
                p0 = fmaf(o0, w3a[nt][0], fmaf(o1, w3b[nt][0], p0));
                p1 = fmaf(o0, w3a[nt][1], fmaf(o1, w3b[nt][1], p1));
                p2 = fmaf(o0, w3a[nt][2], fmaf(o1, w3b[nt][2], p2));
            }
            // interleaved quad reductions (independent chains)
            p0 += __shfl_xor_sync(0xffffffffu, p0, 1);
            p1 += __shfl_xor_sync(0xffffffffu, p1, 1);
            p2 += __shfl_xor_sync(0xffffffffu, p2, 1);
            p0 += __shfl_xor_sync(0xffffffffu, p0, 2);
            p1 += __shfl_xor_sync(0xffffffffu, p1, 2);
            p2 += __shfl_xor_sync(0xffffffffu, p2, 2);
            if ((lane & 3) == 0)
                *(float4*)(pp + (warp * 8 + (lane >> 2)) * 4) =
                    make_float4(p0, p1, p2, 0.0f);
            __syncthreads();                       // pp visible to both warps

            // ---- slot 3: combine + RK4 (ALL lanes, replicated state) ----
            {
                float4 q0 = *(const float4*)(pp + mo * 4);
                float4 q1 = *(const float4*)(pp + (8 + mo) * 4);
                float pa = q0.x + q1.x;
                float pb = q0.y + q1.y;
                float pc = q0.z + q1.z;

                k0  += 0.2f * (0.1f * tanha(pa + sb3[0]));
                k1d += 0.2f * (0.1f * tanha(pb + sb3[1]));
                k2d += 0.2f * (0.1f * tanha(pc + sb3[2]));

                float wgt = (sg == 1 || sg == 2) ? 2.0f : 1.0f;
                s0 = fmaf(wgt, k0,  s0);
                s1 = fmaf(wgt, k1d, s1);
                s2 = fmaf(wgt, k2d, s2);

                if (sg < 3) {
                    float st = (sg < 2) ? hd : dt;
                    a0s = y0 + st * k0;
                    a1s = y1 + st * k1d;
                    a2s = y2 + st * k2d;
                    if (repw)
                        *(float4*)(&x_sw[warp][mo * 4]) =
                            make_float4(a0s, a1s, a2s, ec);
                } else {
                    float w6 = dt * (1.0f / 6.0f);
                    y0 += w6 * s0; y1 += w6 * s1; y2 += w6 * s2;
                    if (repw)
                        *(float4*)(&x_sw[warp][mo * 4]) =
                            make_float4(y0, y1, y2, ec);
                    if (rep0) {
                        size_t o = (size_t)(it + 1) * (BN * 3) + (size_t)bo * 3;
                        out[o] = y0; out[o + 1] = y1; out[o + 2] = y2;
                    }
                }
            }
            __syncwarp();                 // warp-private x buffer ready
        }
        ep = ec;
    }
}

extern "C" void kernel_launch(void* const* d_in, const int* in_sizes, int n_in,
                              void* d_out, int out_size) {
    const float* init = (const float*)d_in[0];
    const float* exc  = (const float*)d_in[1];
    const float* ts   = (const float*)d_in[2];
    const float* W1   = (const float*)d_in[3];
    const float* b1   = (const float*)d_in[4];
    const float* W2   = (const float*)d_in[5];
    const float* b2   = (const float*)d_in[6];
    const float* W3   = (const float*)d_in[7];
    const float* b3   = (const float*)d_in[8];
    float* out = (float*)d_out;

    dim3 tb(32, 8);
    dim3 tg(TN / 32, BN / 32);
    transpose_exc<<<tg, tb>>>(exc);
    ode_kernel<<<BN / MPC, 64>>>(init, ts, W1, b1, W2, b2, W3, b3, out);
}

// round 17
// speedup vs baseline: 1.8084x; 1.3900x over previous
#include <cuda_runtime.h>
#include <cuda_fp16.h>

typedef unsigned int uint32;

#define BN 8192
#define TN 2048
#define MPC 8    // muscles per CTA (rows 0..7 of the 16-row MMA tile)

// Transposed excitation scratch: [T][B] layout for coalesced per-step loads.
__device__ float g_excT[(size_t)TN * BN];

__device__ __forceinline__ float tanha(float x) {
    float y; asm("tanh.approx.f32 %0, %1;" : "=f"(y) : "f"(x)); return y;
}
__device__ __forceinline__ uint32 tanh2(uint32 x) {
    uint32 y; asm("tanh.approx.f16x2 %0, %1;" : "=r"(y) : "r"(x)); return y;
}
__device__ __forceinline__ uint32 packh2(float lo, float hi) {
    __half2 h = __floats2half2_rn(lo, hi);
    return *(uint32*)&h;
}

// exc[B][T] -> g_excT[T][B]
__global__ void transpose_exc(const float* __restrict__ exc) {
    __shared__ float tile[32][33];
    int t0 = blockIdx.x * 32, b0 = blockIdx.y * 32;
    int tx = threadIdx.x, ty = threadIdx.y;
#pragma unroll
    for (int i = 0; i < 32; i += 8)
        tile[ty + i][tx] = exc[(size_t)(b0 + ty + i) * TN + t0 + tx];
    __syncthreads();
#pragma unroll
    for (int i = 0; i < 32; i += 8)
        g_excT[(size_t)(t0 + ty + i) * BN + b0 + tx] = tile[tx][ty + i];
}

// Register-resident tensor-core formulation, ONE barrier per stage.
// CTA = 64 threads (2 warps), 8 muscles. Replica map mo = lane>>2 makes
// each lane's muscle state exactly the A-fragment row it feeds: layer-1
// is computed straight into m16n8k16 A fragments in fp16 registers
// (4 HFMA2 + tanh.f16x2 per neuron pair; rows 8-15 are a zero register).
// No x_s, no h_s, no ldmatrix. Each warp builds the full A redundantly
// and multiplies against its register-resident 32-col W2 half (16 HMMA).
// Only cross-warp traffic: the layer-3 partial combine through a
// double-buffered pp (one __syncthreads per stage, hidden behind the
// physics MUFU chain). W3/b2 live in a smem float4 table.
__global__ __launch_bounds__(64, 7) void ode_kernel(
    const float* __restrict__ init, const float* __restrict__ tspan,
    const float* __restrict__ W1, const float* __restrict__ b1,
    const float* __restrict__ W2, const float* __restrict__ b2,
    const float* __restrict__ W3, const float* __restrict__ b3,
    float* __restrict__ out)
{
    __shared__ __align__(16) float4 pp[2][16];  // double-buffered partials
    __shared__ __align__(16) float4 w3t[64];    // (W3[j][0..2], b2[j])

    const int tid  = threadIdx.x;
    const int lane = tid & 31;
    const int warp = tid >> 5;

    // one-time staging: w3t[j] = {W3[j][0], W3[j][1], W3[j][2], b2[j]}
    w3t[tid] = make_float4(W3[tid * 3], W3[tid * 3 + 1], W3[tid * 3 + 2],
                           b2[tid]);
    const float b30 = b3[0], b31 = b3[1], b32 = b3[2];

    // W1 columns (fp16 pairs) for this lane's 16 A-fragment neurons:
    // pair p (ck = p>>1, half = p&1): j0 = ck*16 + half*8 + (lane&3)*2
    uint32 w1h[8][4];
    uint32 b1h[8];
#pragma unroll
    for (int p = 0; p < 8; p++) {
        int j0 = (p >> 1) * 16 + (p & 1) * 8 + (lane & 3) * 2;
#pragma unroll
        for (int i = 0; i < 4; i++)
            w1h[p][i] = packh2(W1[i * 64 + j0], W1[i * 64 + j0 + 1]);
        b1h[p] = packh2(b1[j0], b1[j0 + 1]);
    }

    // W2 B-fragments (m16n8k16, col layout): n = warp*32 + nt*8 + lane/4,
    // k = ck*16 + (lane%4)*2 (+1, +8, +9). 16 fragments x 2 regs.
    uint32 bfrag[4][4][2];
#pragma unroll
    for (int nt = 0; nt < 4; nt++) {
#pragma unroll
        for (int ck = 0; ck < 4; ck++) {
            int n  = warp * 32 + nt * 8 + (lane >> 2);
            int k0 = ck * 16 + (lane & 3) * 2;
            bfrag[nt][ck][0] = packh2(W2[k0 * 64 + n], W2[(k0 + 1) * 64 + n]);
            bfrag[nt][ck][1] = packh2(W2[(k0 + 8) * 64 + n], W2[(k0 + 9) * 64 + n]);
        }
    }

    // replica map: muscle = A-fragment row of this lane; 4 replicas/warp
    const int  mo   = lane >> 2;
    const bool rep0 = (warp == 0) && ((lane & 3) == 0);
    const int  bo = blockIdx.x * MPC + mo;

    float y0 = init[bo * 3 + 0];
    float y1 = init[bo * 3 + 1];
    float y2 = init[bo * 3 + 2];
    float ep = g_excT[bo];               // k1 at step 0 uses exc[:, 0]
    float tprev = tspan[0];
    if (rep0) {
        out[bo * 3 + 0] = y0; out[bo * 3 + 1] = y1; out[bo * 3 + 2] = y2;
    }
    __syncthreads();                      // w3t ready

#pragma unroll 1
    for (int it = 0; it < TN - 1; it++) {
        float ec    = g_excT[(size_t)it * BN + bo];  // exc[:, it] for k2/k3/k4
        float tnext = tspan[it + 1];
        float dt    = tnext - tprev;
        tprev = tnext;
        float hd  = 0.5f * dt;
        float a0s = y0, a1s = y1, a2s = y2;
        float s0 = 0.f, s1 = 0.f, s2 = 0.f;

#pragma unroll 1
        for (int sg = 0; sg < 4; sg++) {
            float e = (sg == 0) ? ep : ec;

            // ---- layer-1 straight into A fragments (fp16) ----
            uint32 xx0 = packh2(a0s, a0s);
            uint32 xx1 = packh2(a1s, a1s);
            uint32 xx2 = packh2(a2s, a2s);
            uint32 xx3 = packh2(e, e);
            uint32 hf[8];
#pragma unroll
            for (int p = 0; p < 8; p++) {
                __half2 acc = __hfma2(*(__half2*)&w1h[p][0], *(__half2*)&xx0,
                                      *(__half2*)&b1h[p]);
                acc = __hfma2(*(__half2*)&w1h[p][1], *(__half2*)&xx1, acc);
                acc = __hfma2(*(__half2*)&w1h[p][2], *(__half2*)&xx2, acc);
                acc = __hfma2(*(__half2*)&w1h[p][3], *(__half2*)&xx3, acc);
                hf[p] = tanh2(*(uint32*)&acc);
            }

            // ---- HMMA per n-tile + fused layer-3 epilogue ----
            float p0 = 0.f, p1 = 0.f, p2 = 0.f;
            uint32 zr = 0;
#pragma unroll
            for (int nt = 0; nt < 4; nt++) {
                float c0 = 0.f, c1 = 0.f, c2 = 0.f, c3 = 0.f;
#pragma unroll
                for (int ck = 0; ck < 4; ck++) {
                    asm volatile(
                        "mma.sync.aligned.m16n8k16.row.col.f32.f16.f16.f32 "
                        "{%0,%1,%2,%3}, {%4,%5,%6,%7}, {%8,%9}, {%0,%1,%2,%3};"
                        : "+f"(c0), "+f"(c1), "+f"(c2), "+f"(c3)
                        : "r"(hf[2 * ck]), "r"(zr), "r"(hf[2 * ck + 1]), "r"(zr),
                          "r"(bfrag[nt][ck][0]), "r"(bfrag[nt][ck][1]));
                }
                // cols j0 = warp*32 + nt*8 + (lane&3)*2, j0+1
                int idx = (warp * 16 + nt * 4 + (lane & 3)) * 2;
                float4 wa = w3t[idx];
                float4 wb = w3t[idx + 1];
                float o0 = tanha(c0 + wa.w);
                float o1 = tanha(c1 + wb.w);
                p0 = fmaf(o0, wa.x, fmaf(o1, wb.x, p0));
                p1 = fmaf(o0, wa.y, fmaf(o1, wb.y, p1));
                p2 = fmaf(o0, wa.z, fmaf(o1, wb.z, p2));
            }
            // quad reduce (4 lanes of this muscle within the warp)
            p0 += __shfl_xor_sync(0xffffffffu, p0, 1);
            p1 += __shfl_xor_sync(0xffffffffu, p1, 1);
            p2 += __shfl_xor_sync(0xffffffffu, p2, 1);
            p0 += __shfl_xor_sync(0xffffffffu, p0, 2);
            p1 += __shfl_xor_sync(0xffffffffu, p1, 2);
            p2 += __shfl_xor_sync(0xffffffffu, p2, 2);
            if ((lane & 3) == 0)
                pp[sg & 1][warp * 8 + mo] = make_float4(p0, p1, p2, 0.0f);

            // ---- physics (all lanes; hides the barrier wait) ----
            float k0, k1d, k2d;
            {
                float lM   = fminf(fmaxf(a0s, 0.0445f), 0.1424f);
                float act  = fminf(fmaxf(a1s, 0.01f), 1.0f);
                float fat  = fminf(fmaxf(a2s, 0.0f), 1.0f);
                float aeff = act * (1.0f - fat);
                // L0*sin(PENN0) = 0.089*sin(0.0873)
                float sinp = fminf(__fdividef(0.00775983457f, lM), 0.99f);
                float cosp = sqrtf(1.0f - sinp * sinp);
                // LMT_DEFAULT = 0.126 + 0.089*cos(0.0873)
                float lT   = 0.214661068f - lM * cosp;
                float epsT = (lT - 0.126f) * (1.0f / 0.126f);
                float fT   = (epsT > 0.0f) ? 0.2f * (__expf(35.0f * epsT) - 1.0f) : 0.0f;
                float lN   = lM * (1.0f / 0.089f);
                float ddv  = lN - 1.0f;
                float fL   = __expf(-ddv * ddv * (1.0f / 0.45f));
                float fPE  = (lN > 1.0f)
                           ? (__expf(ddv * (5.0f / 0.6f)) - 1.0f) * (1.0f / 147.4131591f)
                           : 0.0f;
                float fV   = __fdividef(__fdividef(fT, cosp) - fPE, aeff * fL + 0.001f);
                float vN   = fminf(fmaxf(__fdividef(fV - 1.0f, 1.0f + fabsf(fV) * 4.0f),
                                         -1.0f), 1.5f);
                k0   = 0.89f * vN;                        // VMAX*L0*vN
                float tau = (e > act) ? 0.01f * (0.5f + 1.5f * act)
                                      : __fdividef(0.04f, 0.5f + 1.5f * act);
                k1d  = __fdividef(e - act, tau);
                k2d  = 0.01f * aeff * (1.0f - fat) - 0.002f * (1.0f - aeff) * fat;
            }
            __syncthreads();              // pp visible to both warps

            // ---- combine + RK4 (all lanes, replicated per quad) ----
            {
                float4 q0 = pp[sg & 1][mo];
                float4 q1 = pp[sg & 1][8 + mo];
                float pa = q0.x + q1.x;
                float pb = q0.y + q1.y;
                float pc = q0.z + q1.z;

                k0  += 0.2f * (0.1f * tanha(pa + b30));
                k1d += 0.2f * (0.1f * tanha(pb + b31));
                k2d += 0.2f * (0.1f * tanha(pc + b32));

                float wgt = (sg == 1 || sg == 2) ? 2.0f : 1.0f;
                s0 = fmaf(wgt, k0,  s0);
                s1 = fmaf(wgt, k1d, s1);
                s2 = fmaf(wgt, k2d, s2);

                if (sg < 3) {
                    float st = (sg < 2) ? hd : dt;
                    a0s = y0 + st * k0;
                    a1s = y1 + st * k1d;
                    a2s = y2 + st * k2d;
                } else {
                    float w6 = dt * (1.0f / 6.0f);
                    y0 += w6 * s0; y1 += w6 * s1; y2 += w6 * s2;
                    if (rep0) {
                        size_t o = (size_t)(it + 1) * (BN * 3) + (size_t)bo * 3;
                        out[o] = y0; out[o + 1] = y1; out[o + 2] = y2;
                    }
                }
            }
        }
        ep = ec;
    }
}

extern "C" void kernel_launch(void* const* d_in, const int* in_sizes, int n_in,
                              void* d_out, int out_size) {
    const float* init = (const float*)d_in[0];
    const float* exc  = (const float*)d_in[1];
    const float* ts   = (const float*)d_in[2];
    const float* W1   = (const float*)d_in[3];
    const float* b1   = (const float*)d_in[4];
    const float* W2   = (const float*)d_in[5];
    const float* b2   = (const float*)d_in[6];
    const float* W3   = (const float*)d_in[7];
    const float* b3   = (const float*)d_in[8];
    float* out = (float*)d_out;

    dim3 tb(32, 8);
    dim3 tg(TN / 32, BN / 32);
    transpose_exc<<<tg, tb>>>(exc);
    ode_kernel<<<BN / MPC, 64>>>(init, ts, W1, b1, W2, b2, W3, b3, out);
}